// round 7
// baseline (speedup 1.0000x reference)
#include <cuda_runtime.h>
#include <cuda_fp16.h>
#include <cuda_bf16.h>
#include <cstdint>
#include <cstring>

// LUT fp16 SiLU: out = fp32( k[li]*h + b[li] ), h = fp16(x), li = (bits(h)>>6)&0x3FF.
// Raw bit-field index is exact for ALL inputs (normals/zero/inf by construction;
// subnormals hit lvl-0 entries that equal the reference's (lvl=1,mi=0) entry
// exactly; NaNs hit lvl-31 entries that are NaN and propagate through k*x+b).
// fp16 math: separate HMUL2 + HADD2 (two roundings/lane) to match jnp float16.
//
// Persistent grid-stride form: 1184 CTAs (148 SMs x 8), LUT loaded once per CTA.
// Table identification inline: b_table[0]==0.0 exactly, k_table[0]==0.5 exactly,
// and the bit-encoding of 0.5 identifies the staged dtype (fp16/fp32/bf16).

__device__ __forceinline__ unsigned h2_to_u(__half2 h) {
    unsigned u; memcpy(&u, &h, 4); return u;
}
__device__ __forceinline__ __half2 u_to_h2(unsigned u) {
    __half2 h; memcpy(&h, &u, 4); return h;
}

__device__ __forceinline__ float4 proc4(float4 v, const __half2* lut)
{
    __half2 h01 = __floats2half2_rn(v.x, v.y);
    __half2 h23 = __floats2half2_rn(v.z, v.w);
    unsigned u01 = h2_to_u(h01);
    unsigned u23 = h2_to_u(h23);

    unsigned li0 = (u01 >> 6) & 0x3FFu;
    unsigned li1 =  u01 >> 22;
    unsigned li2 = (u23 >> 6) & 0x3FFu;
    unsigned li3 =  u23 >> 22;

    unsigned kb0 = h2_to_u(lut[li0]);
    unsigned kb1 = h2_to_u(lut[li1]);
    unsigned kb2 = h2_to_u(lut[li2]);
    unsigned kb3 = h2_to_u(lut[li3]);

    // (k0,b0),(k1,b1) -> (k0,k1),(b0,b1)
    __half2 k01 = u_to_h2(__byte_perm(kb0, kb1, 0x5410));
    __half2 b01 = u_to_h2(__byte_perm(kb0, kb1, 0x7632));
    __half2 k23 = u_to_h2(__byte_perm(kb2, kb3, 0x5410));
    __half2 b23 = u_to_h2(__byte_perm(kb2, kb3, 0x7632));

    __half2 r01 = __hadd2(__hmul2(k01, h01), b01);
    __half2 r23 = __hadd2(__hmul2(k23, h23), b23);

    float2 f01 = __half22float2(r01);
    float2 f23 = __half22float2(r23);
    return make_float4(f01.x, f01.y, f23.x, f23.y);
}

__global__ __launch_bounds__(256)
void lut_silu_kernel(const float4* __restrict__ x,
                     const void* __restrict__ tA,
                     const void* __restrict__ tB,
                     float4* __restrict__ out,
                     int n4)
{
    __shared__ __half2 lut[1024];

    // Inline table identification (uniform broadcast loads, once per CTA).
    unsigned wA = ((const unsigned*)tA)[0];
    unsigned wB = ((const unsigned*)tB)[0];
    bool swp = (wA == 0u);                    // b_table[0] == 0.0 exactly
    unsigned kw = swp ? wB : wA;              // k_table[0] == 0.5 exactly
    int dt;
    if (kw == 0x3F000000u)              dt = 1;  // fp32(0.5)
    else if ((kw & 0xFFFFu) == 0x3F00u) dt = 2;  // bf16(0.5) low half
    else                                dt = 0;  // fp16(0.5)=0x3800 low half
    const void* kp = swp ? tB : tA;
    const void* bp = swp ? tA : tB;

    for (int i = threadIdx.x; i < 1024; i += blockDim.x) {
        __half kh, bh;
        if (dt == 1) {
            kh = __float2half(((const float*)kp)[i]);
            bh = __float2half(((const float*)bp)[i]);
        } else if (dt == 2) {
            kh = __float2half(__bfloat162float(((const __nv_bfloat16*)kp)[i]));
            bh = __float2half(__bfloat162float(((const __nv_bfloat16*)bp)[i]));
        } else {
            kh = ((const __half*)kp)[i];
            bh = ((const __half*)bp)[i];
        }
        lut[i] = __halves2half2(kh, bh);
    }
    __syncthreads();

    // Persistent grid-stride loop, 2 front-batched float4 per iteration.
    int stride = gridDim.x * blockDim.x;          // threads in grid
    int tid = blockIdx.x * blockDim.x + threadIdx.x;

    int i0 = tid;
    for (;;) {
        int i1 = i0 + stride;
        if (i1 < n4) {
            float4 v0 = x[i0];
            float4 v1 = x[i1];
            out[i0] = proc4(v0, lut);
            out[i1] = proc4(v1, lut);
        } else {
            if (i0 < n4) {
                float4 v0 = x[i0];
                out[i0] = proc4(v0, lut);
            }
            break;
        }
        i0 = i1 + stride;
    }
}

extern "C" void kernel_launch(void* const* d_in, const int* in_sizes, int n_in,
                              void* d_out, int out_size)
{
    // x = the large input; the other two are the 1024-entry tables.
    int xi = 0;
    for (int i = 1; i < n_in; i++)
        if (in_sizes[i] > in_sizes[xi]) xi = i;

    const void* tabs[2];
    int t = 0;
    for (int i = 0; i < n_in && t < 2; i++)
        if (i != xi) tabs[t++] = d_in[i];

    const float* x = (const float*)d_in[xi];
    float* out = (float*)d_out;

    int n  = in_sizes[xi];
    int n4 = n >> 2;

    int threads = 256;
    int blocks  = 148 * 8;   // persistent: one full wave at max occupancy
    lut_silu_kernel<<<blocks, threads>>>(
        (const float4*)x, tabs[0], tabs[1], (float4*)out, n4);
}

// round 8
// speedup vs baseline: 1.1454x; 1.1454x over previous
#include <cuda_runtime.h>
#include <cuda_fp16.h>
#include <cuda_bf16.h>
#include <cstdint>
#include <cstring>

// LUT fp16 SiLU: out = fp32( k[li]*h + b[li] ), h = fp16(x), li = (bits(h)>>6)&0x3FF.
// Raw bit-field index is exact for ALL inputs (normals/zero/inf by construction;
// subnormals hit lvl-0 entries that equal the reference's (lvl=1,mi=0) entry
// exactly; NaNs hit lvl-31 entries that are NaN and propagate through k*x+b).
// fp16 math: separate HMUL2 + HADD2 (two roundings/lane) to match jnp float16.
//
// R6 shape (2x float4/thread, grid 32768) + write-through stores (__stwt) to
// keep dirty-writeback traffic out of the read stream's LTS path.
// Table identification inline: b_table[0]==0.0 exactly, k_table[0]==0.5 exactly,
// bit-encoding of 0.5 identifies the staged dtype (fp16/fp32/bf16).

__device__ __forceinline__ unsigned h2_to_u(__half2 h) {
    unsigned u; memcpy(&u, &h, 4); return u;
}
__device__ __forceinline__ __half2 u_to_h2(unsigned u) {
    __half2 h; memcpy(&h, &u, 4); return h;
}

__device__ __forceinline__ float4 proc4(float4 v, const __half2* lut)
{
    __half2 h01 = __floats2half2_rn(v.x, v.y);
    __half2 h23 = __floats2half2_rn(v.z, v.w);
    unsigned u01 = h2_to_u(h01);
    unsigned u23 = h2_to_u(h23);

    unsigned li0 = (u01 >> 6) & 0x3FFu;
    unsigned li1 =  u01 >> 22;
    unsigned li2 = (u23 >> 6) & 0x3FFu;
    unsigned li3 =  u23 >> 22;

    unsigned kb0 = h2_to_u(lut[li0]);
    unsigned kb1 = h2_to_u(lut[li1]);
    unsigned kb2 = h2_to_u(lut[li2]);
    unsigned kb3 = h2_to_u(lut[li3]);

    // (k0,b0),(k1,b1) -> (k0,k1),(b0,b1)
    __half2 k01 = u_to_h2(__byte_perm(kb0, kb1, 0x5410));
    __half2 b01 = u_to_h2(__byte_perm(kb0, kb1, 0x7632));
    __half2 k23 = u_to_h2(__byte_perm(kb2, kb3, 0x5410));
    __half2 b23 = u_to_h2(__byte_perm(kb2, kb3, 0x7632));

    __half2 r01 = __hadd2(__hmul2(k01, h01), b01);
    __half2 r23 = __hadd2(__hmul2(k23, h23), b23);

    float2 f01 = __half22float2(r01);
    float2 f23 = __half22float2(r23);
    return make_float4(f01.x, f01.y, f23.x, f23.y);
}

__global__ __launch_bounds__(256)
void lut_silu_kernel(const float4* __restrict__ x,
                     const void* __restrict__ tA,
                     const void* __restrict__ tB,
                     float4* __restrict__ out,
                     int n4)
{
    __shared__ __half2 lut[1024];

    // Inline table identification (uniform broadcast loads, once per CTA).
    unsigned wA = ((const unsigned*)tA)[0];
    unsigned wB = ((const unsigned*)tB)[0];
    bool swp = (wA == 0u);                    // b_table[0] == 0.0 exactly
    unsigned kw = swp ? wB : wA;              // k_table[0] == 0.5 exactly
    int dt;
    if (kw == 0x3F000000u)              dt = 1;  // fp32(0.5)
    else if ((kw & 0xFFFFu) == 0x3F00u) dt = 2;  // bf16(0.5) low half
    else                                dt = 0;  // fp16(0.5)=0x3800 low half
    const void* kp = swp ? tB : tA;
    const void* bp = swp ? tA : tB;

    for (int i = threadIdx.x; i < 1024; i += blockDim.x) {
        __half kh, bh;
        if (dt == 1) {
            kh = __float2half(((const float*)kp)[i]);
            bh = __float2half(((const float*)bp)[i]);
        } else if (dt == 2) {
            kh = __float2half(__bfloat162float(((const __nv_bfloat16*)kp)[i]));
            bh = __float2half(__bfloat162float(((const __nv_bfloat16*)bp)[i]));
        } else {
            kh = ((const __half*)kp)[i];
            bh = ((const __half*)bp)[i];
        }
        lut[i] = __halves2half2(kh, bh);
    }
    __syncthreads();

    // 8 elements (2x float4) per thread, both loads front-batched.
    int base = blockIdx.x * (blockDim.x * 2) + threadIdx.x;
    int i0 = base;
    int i1 = base + blockDim.x;

    bool p0 = i0 < n4;
    bool p1 = i1 < n4;
    float4 v0, v1;
    if (p0) v0 = x[i0];
    if (p1) v1 = x[i1];

    if (p0) __stwt(&out[i0], proc4(v0, lut));
    if (p1) __stwt(&out[i1], proc4(v1, lut));
}

extern "C" void kernel_launch(void* const* d_in, const int* in_sizes, int n_in,
                              void* d_out, int out_size)
{
    // x = the large input; the other two are the 1024-entry tables.
    int xi = 0;
    for (int i = 1; i < n_in; i++)
        if (in_sizes[i] > in_sizes[xi]) xi = i;

    const void* tabs[2];
    int t = 0;
    for (int i = 0; i < n_in && t < 2; i++)
        if (i != xi) tabs[t++] = d_in[i];

    const float* x = (const float*)d_in[xi];
    float* out = (float*)d_out;

    int n  = in_sizes[xi];
    int n4 = n >> 2;

    int threads = 256;
    int elemsPerBlock = threads * 2;          // 2 float4 per thread
    int blocks = (n4 + elemsPerBlock - 1) / elemsPerBlock;
    lut_silu_kernel<<<blocks, threads>>>(
        (const float4*)x, tabs[0], tabs[1], (float4*)out, n4);
}

// round 9
// speedup vs baseline: 1.1732x; 1.0243x over previous
#include <cuda_runtime.h>
#include <cuda_fp16.h>
#include <cuda_bf16.h>
#include <cstdint>
#include <cstring>

// LUT fp16 SiLU: out = fp32( k[li]*h + b[li] ), h = fp16(x), li = (bits(h)>>6)&0x3FF.
// Raw bit-field index is exact for ALL inputs (normals/zero/inf by construction;
// subnormals hit lvl-0 entries that equal the reference's (lvl=1,mi=0) entry
// exactly; NaNs hit lvl-31 entries that are NaN and propagate through k*x+b).
// fp16 math: separate HMUL2 + HADD2 (two roundings/lane) to match jnp float16.
//
// R6 shape (2x float4/thread, grid 32768, default stores) with __ldcg reads:
// streaming loads bypass L1 allocation, relieving the L1tex unit shared by
// LDG fills, STG, and the per-element LDS LUT lookups.
// Table identification inline: b_table[0]==0.0 exactly, k_table[0]==0.5 exactly,
// bit-encoding of 0.5 identifies the staged dtype (fp16/fp32/bf16).

__device__ __forceinline__ unsigned h2_to_u(__half2 h) {
    unsigned u; memcpy(&u, &h, 4); return u;
}
__device__ __forceinline__ __half2 u_to_h2(unsigned u) {
    __half2 h; memcpy(&h, &u, 4); return h;
}

__device__ __forceinline__ float4 proc4(float4 v, const __half2* lut)
{
    __half2 h01 = __floats2half2_rn(v.x, v.y);
    __half2 h23 = __floats2half2_rn(v.z, v.w);
    unsigned u01 = h2_to_u(h01);
    unsigned u23 = h2_to_u(h23);

    unsigned li0 = (u01 >> 6) & 0x3FFu;
    unsigned li1 =  u01 >> 22;
    unsigned li2 = (u23 >> 6) & 0x3FFu;
    unsigned li3 =  u23 >> 22;

    unsigned kb0 = h2_to_u(lut[li0]);
    unsigned kb1 = h2_to_u(lut[li1]);
    unsigned kb2 = h2_to_u(lut[li2]);
    unsigned kb3 = h2_to_u(lut[li3]);

    // (k0,b0),(k1,b1) -> (k0,k1),(b0,b1)
    __half2 k01 = u_to_h2(__byte_perm(kb0, kb1, 0x5410));
    __half2 b01 = u_to_h2(__byte_perm(kb0, kb1, 0x7632));
    __half2 k23 = u_to_h2(__byte_perm(kb2, kb3, 0x5410));
    __half2 b23 = u_to_h2(__byte_perm(kb2, kb3, 0x7632));

    __half2 r01 = __hadd2(__hmul2(k01, h01), b01);
    __half2 r23 = __hadd2(__hmul2(k23, h23), b23);

    float2 f01 = __half22float2(r01);
    float2 f23 = __half22float2(r23);
    return make_float4(f01.x, f01.y, f23.x, f23.y);
}

__global__ __launch_bounds__(256)
void lut_silu_kernel(const float4* __restrict__ x,
                     const void* __restrict__ tA,
                     const void* __restrict__ tB,
                     float4* __restrict__ out,
                     int n4)
{
    __shared__ __half2 lut[1024];

    // Inline table identification (uniform broadcast loads, once per CTA).
    unsigned wA = ((const unsigned*)tA)[0];
    unsigned wB = ((const unsigned*)tB)[0];
    bool swp = (wA == 0u);                    // b_table[0] == 0.0 exactly
    unsigned kw = swp ? wB : wA;              // k_table[0] == 0.5 exactly
    int dt;
    if (kw == 0x3F000000u)              dt = 1;  // fp32(0.5)
    else if ((kw & 0xFFFFu) == 0x3F00u) dt = 2;  // bf16(0.5) low half
    else                                dt = 0;  // fp16(0.5)=0x3800 low half
    const void* kp = swp ? tB : tA;
    const void* bp = swp ? tA : tB;

    for (int i = threadIdx.x; i < 1024; i += blockDim.x) {
        __half kh, bh;
        if (dt == 1) {
            kh = __float2half(((const float*)kp)[i]);
            bh = __float2half(((const float*)bp)[i]);
        } else if (dt == 2) {
            kh = __float2half(__bfloat162float(((const __nv_bfloat16*)kp)[i]));
            bh = __float2half(__bfloat162float(((const __nv_bfloat16*)bp)[i]));
        } else {
            kh = ((const __half*)kp)[i];
            bh = ((const __half*)bp)[i];
        }
        lut[i] = __halves2half2(kh, bh);
    }
    __syncthreads();

    // 8 elements (2x float4) per thread, both loads front-batched, L1-bypass reads.
    int base = blockIdx.x * (blockDim.x * 2) + threadIdx.x;
    int i0 = base;
    int i1 = base + blockDim.x;

    bool p0 = i0 < n4;
    bool p1 = i1 < n4;
    float4 v0, v1;
    if (p0) v0 = __ldcg(&x[i0]);
    if (p1) v1 = __ldcg(&x[i1]);

    if (p0) out[i0] = proc4(v0, lut);
    if (p1) out[i1] = proc4(v1, lut);
}

extern "C" void kernel_launch(void* const* d_in, const int* in_sizes, int n_in,
                              void* d_out, int out_size)
{
    // x = the large input; the other two are the 1024-entry tables.
    int xi = 0;
    for (int i = 1; i < n_in; i++)
        if (in_sizes[i] > in_sizes[xi]) xi = i;

    const void* tabs[2];
    int t = 0;
    for (int i = 0; i < n_in && t < 2; i++)
        if (i != xi) tabs[t++] = d_in[i];

    const float* x = (const float*)d_in[xi];
    float* out = (float*)d_out;

    int n  = in_sizes[xi];
    int n4 = n >> 2;

    int threads = 256;
    int elemsPerBlock = threads * 2;          // 2 float4 per thread
    int blocks = (n4 + elemsPerBlock - 1) / elemsPerBlock;
    lut_silu_kernel<<<blocks, threads>>>(
        (const float4*)x, tabs[0], tabs[1], (float4*)out, n4);
}